// round 1
// baseline (speedup 1.0000x reference)
#include <cuda_runtime.h>

#define D 128
#define MAXN 50000
#define MAXE 800000

// ---------------- scratch (device globals; no allocation allowed) ----------
__device__ float g_h[(size_t)MAXN * D];        // current hidden state
__device__ float g_t[(size_t)MAXN * D];        // h @ W
__device__ float g_dinv[MAXN];
__device__ int   g_deg[MAXN];
__device__ int   g_rowptr[MAXN + 1];
__device__ int   g_cursor[MAXN];
__device__ int   g_col[MAXE];
__device__ float g_wgt[MAXE];

// ---------------- degree / CSR build ---------------------------------------
__global__ void k_init_deg(int n) {
    int i = blockIdx.x * blockDim.x + threadIdx.x;
    if (i < n) g_deg[i] = 0;
}

__global__ void k_count_deg(const int* __restrict__ dst, int e) {
    int i = blockIdx.x * blockDim.x + threadIdx.x;
    if (i < e) atomicAdd(&g_deg[dst[i]], 1);
}

__global__ void k_dinv(int n) {
    int i = blockIdx.x * blockDim.x + threadIdx.x;
    if (i < n) g_dinv[i] = rsqrtf((float)(g_deg[i] + 1));  // +1 self loop
}

// Single-block exclusive scan over g_deg -> g_rowptr (50k elements: trivial time)
__global__ void k_scan(int n) {
    __shared__ int sdata[1024];
    __shared__ int carry;
    int tid = threadIdx.x;
    if (tid == 0) { carry = 0; g_rowptr[0] = 0; }
    __syncthreads();
    for (int base = 0; base < n; base += 1024) {
        int i = base + tid;
        int v = (i < n) ? g_deg[i] : 0;
        sdata[tid] = v;
        __syncthreads();
        // Hillis-Steele inclusive scan
        #pragma unroll
        for (int off = 1; off < 1024; off <<= 1) {
            int t = (tid >= off) ? sdata[tid - off] : 0;
            __syncthreads();
            sdata[tid] += t;
            __syncthreads();
        }
        if (i < n) g_rowptr[i + 1] = carry + sdata[tid];
        __syncthreads();
        if (tid == 0) carry += sdata[1023];
        __syncthreads();
    }
}

__global__ void k_copy_cursor(int n) {
    int i = blockIdx.x * blockDim.x + threadIdx.x;
    if (i < n) g_cursor[i] = g_rowptr[i];
}

__global__ void k_fill_edges(const int* __restrict__ src, const int* __restrict__ dst, int e) {
    int i = blockIdx.x * blockDim.x + threadIdx.x;
    if (i < e) {
        int s = src[i], d = dst[i];
        int pos = atomicAdd(&g_cursor[d], 1);
        g_col[pos] = s;
        g_wgt[pos] = g_dinv[s] * g_dinv[d];
    }
}

// ---------------- GEMM: T[n,128] = H[n,128] @ W[128,128] --------------------
// Block: 256 threads, 64-row tile. Warp handles 8 rows x 128 cols;
// each thread: 8 rows x 4 cols in registers. Full W (64KB) + H tile (32KB) in smem.
#define GEMM_ROWS 64
#define GEMM_SMEM ((D * D + GEMM_ROWS * D) * 4)

__global__ __launch_bounds__(256, 2) void k_gemm(
    const float* __restrict__ H, const float* __restrict__ W,
    float* __restrict__ T, int n)
{
    extern __shared__ float smem[];
    float* sW = smem;                 // [128][128]
    float* sH = smem + D * D;         // [64][128]
    int tid = threadIdx.x;

    float4* sW4 = (float4*)sW;
    const float4* W4 = (const float4*)W;
    #pragma unroll
    for (int i = tid; i < D * D / 4; i += 256) sW4[i] = W4[i];

    int row0 = blockIdx.x * GEMM_ROWS;
    float4* sH4 = (float4*)sH;
    #pragma unroll
    for (int i = tid; i < GEMM_ROWS * D / 4; i += 256) {
        int r = i >> 5;        // 32 float4 per row
        int c4 = i & 31;
        int gr = row0 + r;
        float4 v = make_float4(0.f, 0.f, 0.f, 0.f);
        if (gr < n) v = ((const float4*)(H + (size_t)gr * D))[c4];
        sH4[i] = v;
    }
    __syncthreads();

    int warp = tid >> 5, lane = tid & 31;
    int rbase = warp * 8;

    float4 acc[8];
    #pragma unroll
    for (int r = 0; r < 8; r++) acc[r] = make_float4(0.f, 0.f, 0.f, 0.f);

    #pragma unroll 4
    for (int k = 0; k < D; k++) {
        float4 wv = sW4[k * 32 + lane];
        #pragma unroll
        for (int r = 0; r < 8; r++) {
            float hv = sH[(rbase + r) * D + k];
            acc[r].x = fmaf(hv, wv.x, acc[r].x);
            acc[r].y = fmaf(hv, wv.y, acc[r].y);
            acc[r].z = fmaf(hv, wv.z, acc[r].z);
            acc[r].w = fmaf(hv, wv.w, acc[r].w);
        }
    }

    #pragma unroll
    for (int r = 0; r < 8; r++) {
        int gr = row0 + rbase + r;
        if (gr < n) ((float4*)(T + (size_t)gr * D))[lane] = acc[r];
    }
}

// ---------------- Aggregation: warp per node --------------------------------
// OUT[i] = sum_{e: dst==i} w_e * T[src_e] + dinv[i]^2 * T[i] + bias
// optional relu; optional residual (+X) on the last layer.
__global__ __launch_bounds__(256) void k_agg(
    const float* __restrict__ T, const float* __restrict__ bias,
    const float* __restrict__ X, float* __restrict__ OUT,
    int n, int do_relu)
{
    int gw = (blockIdx.x * blockDim.x + threadIdx.x) >> 5;
    int lane = threadIdx.x & 31;
    if (gw >= n) return;

    int beg = g_rowptr[gw];
    int end = g_rowptr[gw + 1];
    float di = g_dinv[gw];

    const float4* T4 = (const float4*)T;
    float4 tv = T4[(size_t)gw * 32 + lane];
    float sw = di * di;
    float4 acc = make_float4(tv.x * sw, tv.y * sw, tv.z * sw, tv.w * sw);

    int e = beg;
    // 4-way unrolled edge loop for MLP (L2-latency hiding)
    for (; e + 4 <= end; e += 4) {
        int s0 = g_col[e], s1 = g_col[e + 1], s2 = g_col[e + 2], s3 = g_col[e + 3];
        float w0 = g_wgt[e], w1 = g_wgt[e + 1], w2 = g_wgt[e + 2], w3 = g_wgt[e + 3];
        float4 a = T4[(size_t)s0 * 32 + lane];
        float4 b = T4[(size_t)s1 * 32 + lane];
        float4 c = T4[(size_t)s2 * 32 + lane];
        float4 d = T4[(size_t)s3 * 32 + lane];
        acc.x = fmaf(w0, a.x, acc.x); acc.y = fmaf(w0, a.y, acc.y);
        acc.z = fmaf(w0, a.z, acc.z); acc.w = fmaf(w0, a.w, acc.w);
        acc.x = fmaf(w1, b.x, acc.x); acc.y = fmaf(w1, b.y, acc.y);
        acc.z = fmaf(w1, b.z, acc.z); acc.w = fmaf(w1, b.w, acc.w);
        acc.x = fmaf(w2, c.x, acc.x); acc.y = fmaf(w2, c.y, acc.y);
        acc.z = fmaf(w2, c.z, acc.z); acc.w = fmaf(w2, c.w, acc.w);
        acc.x = fmaf(w3, d.x, acc.x); acc.y = fmaf(w3, d.y, acc.y);
        acc.z = fmaf(w3, d.z, acc.z); acc.w = fmaf(w3, d.w, acc.w);
    }
    for (; e < end; e++) {
        int s = g_col[e];
        float w = g_wgt[e];
        float4 a = T4[(size_t)s * 32 + lane];
        acc.x = fmaf(w, a.x, acc.x); acc.y = fmaf(w, a.y, acc.y);
        acc.z = fmaf(w, a.z, acc.z); acc.w = fmaf(w, a.w, acc.w);
    }

    float4 bv = ((const float4*)bias)[lane];
    acc.x += bv.x; acc.y += bv.y; acc.z += bv.z; acc.w += bv.w;

    if (do_relu) {
        acc.x = fmaxf(acc.x, 0.f); acc.y = fmaxf(acc.y, 0.f);
        acc.z = fmaxf(acc.z, 0.f); acc.w = fmaxf(acc.w, 0.f);
    }
    if (X) {  // residual on last layer
        float4 xv = ((const float4*)X)[(size_t)gw * 32 + lane];
        acc.x += xv.x; acc.y += xv.y; acc.z += xv.z; acc.w += xv.w;
    }
    ((float4*)OUT)[(size_t)gw * 32 + lane] = acc;
}

// ---------------- launch ----------------------------------------------------
extern "C" void kernel_launch(void* const* d_in, const int* in_sizes, int n_in,
                              void* d_out, int out_size)
{
    const float* x  = (const float*)d_in[0];
    const int*   ei = (const int*)d_in[1];
    const float* W0 = (const float*)d_in[2];
    const float* b0 = (const float*)d_in[3];
    const float* W1 = (const float*)d_in[4];
    const float* b1 = (const float*)d_in[5];
    const float* W2 = (const float*)d_in[6];
    const float* b2 = (const float*)d_in[7];
    float* out = (float*)d_out;

    int n = in_sizes[0] / D;
    int e = in_sizes[1] / 2;
    const int* src = ei;
    const int* dst = ei + e;

    cudaFuncSetAttribute(k_gemm, cudaFuncAttributeMaxDynamicSharedMemorySize, GEMM_SMEM);

    int tb = 256;
    int gn = (n + tb - 1) / tb;
    int ge = (e + tb - 1) / tb;

    // Build normalization + CSR (reused across all 3 layers)
    k_init_deg<<<gn, tb>>>(n);
    k_count_deg<<<ge, tb>>>(dst, e);
    k_dinv<<<gn, tb>>>(n);
    k_scan<<<1, 1024>>>(n);
    k_copy_cursor<<<gn, tb>>>(n);
    k_fill_edges<<<ge, tb>>>(src, dst, e);

    int ggemm = (n + GEMM_ROWS - 1) / GEMM_ROWS;
    int gagg  = (n + 7) / 8;   // 8 warps per 256-thread block, warp per node

    // Layer 0: t = x @ W0 ; h = relu(agg(t) + b0)
    k_gemm<<<ggemm, 256, GEMM_SMEM>>>(x, W0, g_t, n);
    k_agg<<<gagg, 256>>>(g_t, b0, nullptr, g_h, n, 1);

    // Layer 1: t = h @ W1 ; h = relu(agg(t) + b1)
    k_gemm<<<ggemm, 256, GEMM_SMEM>>>(g_h, W1, g_t, n);
    k_agg<<<gagg, 256>>>(g_t, b1, nullptr, g_h, n, 1);

    // Layer 2: t = h @ W2 ; out = agg(t) + b2 + x
    k_gemm<<<ggemm, 256, GEMM_SMEM>>>(g_h, W2, g_t, n);
    k_agg<<<gagg, 256>>>(g_t, b2, x, out, n, 0);
}